// round 6
// baseline (speedup 1.0000x reference)
#include <cuda_runtime.h>

#define GRID_S 224
#define DIM 512
#define CELLS (GRID_S * GRID_S)
#define TPB 8   // tokens per block

// Scratch (no device allocations allowed).
// g_map is NEVER cleared: lookups are validated against pos, so stale
// contents (zero-init on first call, previous identical scatter after)
// cannot affect the result -> deterministic without an init pass.
__device__ int   g_map[CELLS];
__device__ float g_wt[9 * DIM];

// Fused prep: scatter cell->token map AND transpose w [DIM][3][3] -> g_wt[k][c]
__global__ void prep_kernel(const int* __restrict__ pos,
                            const float* __restrict__ w, int n) {
    int i = blockIdx.x * blockDim.x + threadIdx.x;
    if (i < n) {
        int r = pos[2 * i];
        int c = pos[2 * i + 1];
        g_map[r * GRID_S + c] = i;
    }
    if (i < 9 * DIM) {
        int c = i / 9;
        int k = i % 9;
        g_wt[k * DIM + c] = w[i];
    }
}

// One block per TPB tokens. 128 threads x float4 = 512 channels.
// Weights live in SMEM (loaded once per block) to keep registers low and
// occupancy high. Mask reductions for all TPB tokens are batched into one
// phase with a SINGLE __syncthreads; the conv phase then runs barrier-free.
__global__ __launch_bounds__(128, 8) void sparse_dwconv_kernel(
    const float* __restrict__ x,
    const int*   __restrict__ pos,
    const float* __restrict__ b,
    float*       __restrict__ out,
    int n)
{
    const int tok0 = blockIdx.x * TPB;
    const int tid = threadIdx.x;
    const int lane = tid & 31;
    const int wid  = tid >> 5;

    __shared__ float s_w[9 * DIM];    // 18 KB transposed weights
    __shared__ int   s_nbr[TPB][9];   // [t][k], k=4 unused (center = self)
    __shared__ float s_wsum[TPB][4];  // per-warp partial channel sums

    // --- Preamble 1: cooperative weight fill (9 float4 per thread) ---
#pragma unroll
    for (int i = 0; i < 9; ++i) {
        const int idx = i * 128 + tid;   // 1152 float4 total
        reinterpret_cast<float4*>(s_w)[idx] =
            reinterpret_cast<const float4*>(g_wt)[idx];
    }

    // --- Preamble 2: validated neighbor lookups (72 threads) ---
    if (tid < TPB * 9) {
        const int t = tid / 9;
        const int k = tid % 9;
        const int tok = tok0 + t;
        int idx = -1;
        if (tok < n && k != 4) {
            const int p0 = pos[2 * tok];
            const int p1 = pos[2 * tok + 1];
            const int kh = k / 3;
            const int kw = k % 3;
            const int r = p0 + kw - 1;   // row axis moves with kw
            const int c = p1 + kh - 1;   // col axis moves with kh
            if (r >= 0 && r < GRID_S && c >= 0 && c < GRID_S) {
                int cand = g_map[r * GRID_S + c];
                if ((unsigned)cand < (unsigned)n &&
                    pos[2 * cand] == r && pos[2 * cand + 1] == c)
                    idx = cand;
            }
        }
        s_nbr[t][k] = idx;
    }

    const int base = tid * 4;

    // --- Phase A: batched mask reductions for all TPB tokens ---
    // 8 independent load+reduce chains overlap; shuffle latency is hidden
    // by ILP instead of being serialized behind per-token barriers.
#pragma unroll
    for (int t = 0; t < TPB; ++t) {
        const int tok = tok0 + t;
        float s = 0.0f;
        if (tok < n) {
            const float4 xc = *reinterpret_cast<const float4*>(
                x + (size_t)tok * DIM + base);
            s = xc.x + xc.y + xc.z + xc.w;
        }
#pragma unroll
        for (int o = 16; o > 0; o >>= 1)
            s += __shfl_xor_sync(0xffffffffu, s, o);
        if (lane == 0) s_wsum[t][wid] = s;
    }

    const float4 bv = *reinterpret_cast<const float4*>(b + base);

    __syncthreads();   // the ONLY block barrier

    // --- Phase B: barrier-free conv + residual + store ---
#pragma unroll 1
    for (int t = 0; t < TPB; ++t) {
        const int tok = tok0 + t;
        if (tok >= n) break;

        const float4 xc = *reinterpret_cast<const float4*>(
            x + (size_t)tok * DIM + base);              // L1 hit (phase A)

        // Center tap from the residual row.
        const float4 wc = *reinterpret_cast<const float4*>(s_w + 4 * DIM + base);
        float4 acc;
        acc.x = wc.x * xc.x;
        acc.y = wc.y * xc.y;
        acc.z = wc.z * xc.z;
        acc.w = wc.w * xc.w;

#pragma unroll
        for (int k = 0; k < 9; ++k) {
            if (k == 4) continue;
            const int nb = s_nbr[t][k];
            if (nb >= 0) {
                const float4 xv = *reinterpret_cast<const float4*>(
                    x + (size_t)nb * DIM + base);
                const float4 wv = *reinterpret_cast<const float4*>(
                    s_w + k * DIM + base);
                acc.x = fmaf(wv.x, xv.x, acc.x);
                acc.y = fmaf(wv.y, xv.y, acc.y);
                acc.z = fmaf(wv.z, xv.z, acc.z);
                acc.w = fmaf(wv.w, xv.w, acc.w);
            }
        }

        const float total = s_wsum[t][0] + s_wsum[t][1]
                          + s_wsum[t][2] + s_wsum[t][3];

        float4 o4;
        if (total != 0.0f) {
            o4.x = xc.x + acc.x + bv.x;
            o4.y = xc.y + acc.y + bv.y;
            o4.z = xc.z + acc.z + bv.z;
            o4.w = xc.w + acc.w + bv.w;
        } else {
            o4 = xc;  // masked cell: conv (incl. bias) zeroed, residual only
        }
        *reinterpret_cast<float4*>(out + (size_t)tok * DIM + base) = o4;
    }
}

extern "C" void kernel_launch(void* const* d_in, const int* in_sizes, int n_in,
                              void* d_out, int out_size) {
    const float* x   = (const float*)d_in[0];   // [1, N, 512]
    const int*   pos = (const int*)  d_in[1];   // [N, 2]
    const float* w   = (const float*)d_in[2];   // [512, 1, 3, 3]
    const float* b   = (const float*)d_in[3];   // [512]
    float* out = (float*)d_out;                 // [1, N, 512]

    const int n = in_sizes[1] / 2;

    const int prep_elems = (n > 9 * DIM) ? n : 9 * DIM;
    prep_kernel<<<(prep_elems + 255) / 256, 256>>>(pos, w, n);
    sparse_dwconv_kernel<<<(n + TPB - 1) / TPB, 128>>>(x, pos, b, out, n);
}